// round 7
// baseline (speedup 1.0000x reference)
#include <cuda_runtime.h>
#include <math.h>

// Shapes fixed by the problem instance
#define KB    4
#define CIN   8
#define COUT  64
#define NLEN  4096
#define SPLIT 16          // blocks per (k,ci) row in zred
#define NB    (KB * COUT) // 256 output rows
#define TWO_PI_OVER_N 0.0015339807878856412f   // 2*pi/4096

// Scratch
__device__ float g_part_r[KB * CIN][SPLIT];
__device__ float g_part_i[KB * CIN][SPLIT];
__device__ float g_Gr[NB];
__device__ float g_Gi[NB];
__device__ float g_cos[NLEN];
__device__ float g_sin[NLEN];
__device__ int   g_count = 0;

// Kernel 1: 512 partial-DFT blocks + 16 phase-table blocks in one launch.
// The LAST partial block to finish also reduces partials -> gated G[256].
__global__ __launch_bounds__(256) void zred_kernel(
    const float* __restrict__ zr, const float* __restrict__ zi,
    const float* __restrict__ A, const float* __restrict__ beta,
    const float* __restrict__ bias, const int* __restrict__ mptr)
{
    const int tid = threadIdx.x;
    const int m   = *mptr;

    if (blockIdx.x >= KB * CIN * SPLIT) {
        // Phase table: components of e^{i*omega*mu}, exact arg reduction.
        const int mu = (blockIdx.x - KB * CIN * SPLIT) * 256 + tid;
        const int p  = (m * mu) & (NLEN - 1);
        float s, c;
        __sincosf(TWO_PI_OVER_N * (float)p, &s, &c);
        g_cos[mu] = c;
        g_sin[mu] = s;
        return;
    }

    const int b     = blockIdx.x >> 4;      // (k*CIN + ci)
    const int split = blockIdx.x & 15;
    const int tg    = split * 256 + tid;    // global sample index

    const int p = (m * tg) & (NLEN - 1);    // exact phase index
    float s, c;
    __sincosf(TWO_PI_OVER_N * (float)p, &s, &c);
    const float x = zr[(size_t)b * NLEN + tg];
    const float y = zi[(size_t)b * NLEN + tg];
    float ar = x * c - y * s;               // e^{+i*omega*t} * z
    float ai = x * s + y * c;

    // warp reduce
#pragma unroll
    for (int off = 16; off > 0; off >>= 1) {
        ar += __shfl_down_sync(0xffffffff, ar, off);
        ai += __shfl_down_sync(0xffffffff, ai, off);
    }
    __shared__ float swr[8], swi[8];
    __shared__ int   s_last;
    __shared__ float sZr[KB * CIN], sZi[KB * CIN];
    if ((tid & 31) == 0) { swr[tid >> 5] = ar; swi[tid >> 5] = ai; }
    __syncthreads();
    if (tid == 0) {
        float tr = 0.f, ti = 0.f;
#pragma unroll
        for (int w = 0; w < 8; w++) { tr += swr[w]; ti += swi[w]; }
        g_part_r[b][split] = tr;
        g_part_i[b][split] = ti;
        __threadfence();                     // publish partial before arriving
        int old = atomicAdd(&g_count, 1);
        s_last = (old == KB * CIN * SPLIT - 1) ? 1 : 0;
        if (s_last) atomicExch(&g_count, 0); // reset for next graph replay
    }
    __syncthreads();
    if (!s_last) return;

    // ---- Last block: all partials are globally visible. Build gated G. ----
    __threadfence();
    if (tid < KB * CIN) {
        float tr = 0.f, ti = 0.f;
#pragma unroll
        for (int sp = 0; sp < SPLIT; sp++) {
            tr += g_part_r[tid][sp];
            ti += g_part_i[tid][sp];
        }
        sZr[tid] = tr;
        sZi[tid] = ti;
    }
    __syncthreads();

    // One thread per (k,co).
    const int k  = tid >> 6;
    const int co = tid & 63;
    float Gr = 0.f, Gi = 0.f;
#pragma unroll
    for (int ci = 0; ci < CIN; ci++) {
        const float a = fabsf(A[co * CIN + ci]);
        float sb, cb;
        __sincosf(beta[co * CIN + ci], &sb, &cb);
        const float Wr = a * cb, Wi = a * sb;
        const float Zr = sZr[k * CIN + ci];
        const float Zi = sZi[k * CIN + ci];
        Gr += Wr * Zr - Wi * Zi;
        Gi += Wr * Zi + Wi * Zr;
    }
    const float mag  = sqrtf(Gr * Gr + Gi * Gi);
    const float gate = (1.f / (1.f + __expf(-(mag + bias[co])))) / (mag + 1e-5f);
    g_Gr[tid] = gate * Gr;
    g_Gi[tid] = gate * Gi;
}

// Kernel 2: pure stream, 2048 thin blocks.
// out_r[b][mu] = Gr*c[mu] + Gi*s[mu];  out_i[b][mu] = Gi*c[mu] - Gr*s[mu].
__global__ __launch_bounds__(128) void out_kernel(float* __restrict__ out)
{
    const int b  = blockIdx.x;              // k*COUT + co
    const float gr = g_Gr[b];
    const float gi = g_Gi[b];

    const int mu0 = blockIdx.y * 512 + threadIdx.x * 4;
    const float4 c4 = *reinterpret_cast<const float4*>(&g_cos[mu0]);
    const float4 s4 = *reinterpret_cast<const float4*>(&g_sin[mu0]);

    float4 vr, vi;
    vr.x = gr * c4.x + gi * s4.x;  vi.x = gi * c4.x - gr * s4.x;
    vr.y = gr * c4.y + gi * s4.y;  vi.y = gi * c4.y - gr * s4.y;
    vr.z = gr * c4.z + gi * s4.z;  vi.z = gi * c4.z - gr * s4.z;
    vr.w = gr * c4.w + gi * s4.w;  vi.w = gi * c4.w - gr * s4.w;

    float* outr = out + (size_t)b * NLEN + mu0;
    float* outi = out + (size_t)NB * NLEN + (size_t)b * NLEN + mu0;
    *reinterpret_cast<float4*>(outr) = vr;
    *reinterpret_cast<float4*>(outi) = vi;
}

extern "C" void kernel_launch(void* const* d_in, const int* in_sizes, int n_in,
                              void* d_out, int out_size)
{
    const float* z_real = (const float*)d_in[0];
    const float* z_imag = (const float*)d_in[1];
    const float* A      = (const float*)d_in[2];
    const float* beta   = (const float*)d_in[3];
    const float* bias   = (const float*)d_in[4];
    const int*   mptr   = (const int*)d_in[5];
    float* out = (float*)d_out;

    zred_kernel<<<KB * CIN * SPLIT + 16, 256>>>(z_real, z_imag, A, beta, bias, mptr);
    dim3 grid(NB, NLEN / 512);
    out_kernel<<<grid, 128>>>(out);
}

// round 9
// speedup vs baseline: 1.0239x; 1.0239x over previous
#include <cuda_runtime.h>
#include <math.h>

// Shapes fixed by the problem instance
#define KB    4
#define CIN   8
#define COUT  64
#define NLEN  4096
#define NROWS (KB * CIN)      // 32 input rows
#define SPLIT 4               // DFT blocks per input row
#define NDFT  (NROWS * SPLIT) // 128 DFT blocks
#define NTAB  16              // table blocks
#define NB    (KB * COUT)     // 256 output rows
#define NBLK  512             // total grid (all co-resident: 512 <= 148*4)
#define TWO_PI_OVER_N 0.0015339807878856412f   // 2*pi/4096

// Scratch
__device__ float g_part_r[NROWS][SPLIT];
__device__ float g_part_i[NROWS][SPLIT];
__device__ float g_Gr[NB];
__device__ float g_Gi[NB];
__device__ float g_cos[NLEN];
__device__ float g_sin[NLEN];
__device__ int   g_count = 0;
__device__ int   g_flag  = 0;   // generation counter (sense-reversal)

__global__ __launch_bounds__(256) void fused_kernel(
    const float* __restrict__ zr, const float* __restrict__ zi,
    const float* __restrict__ A, const float* __restrict__ beta,
    const float* __restrict__ bias, const int* __restrict__ mptr,
    float* __restrict__ out)
{
    const int tid = threadIdx.x;
    const int bx  = blockIdx.x;

    __shared__ int   s_init, s_last;
    __shared__ float swr[8], swi[8];
    __shared__ float sZr[NROWS], sZi[NROWS];

    if (tid == 0) {
        s_init = *((volatile int*)&g_flag);   // generation at entry (pre-increment)
        s_last = 0;
    }
    __syncthreads();

    const int m = *mptr;

    // ---------------- Phase A ----------------
    if (bx < NDFT) {
        // Partial DFT: row b, quarter 'split', 4 consecutive samples per thread.
        const int b     = bx >> 2;
        const int split = bx & 3;
        const int base  = split * 1024 + tid * 4;

        const float4 x4 = *reinterpret_cast<const float4*>(zr + (size_t)b * NLEN + base);
        const float4 y4 = *reinterpret_cast<const float4*>(zi + (size_t)b * NLEN + base);
        const float xs[4] = {x4.x, x4.y, x4.z, x4.w};
        const float ys[4] = {y4.x, y4.y, y4.z, y4.w};

        float ar = 0.f, ai = 0.f;
#pragma unroll
        for (int j = 0; j < 4; j++) {
            const int p = (m * (base + j)) & (NLEN - 1);   // exact phase index
            float s, c;
            __sincosf(TWO_PI_OVER_N * (float)p, &s, &c);
            ar += xs[j] * c - ys[j] * s;                    // e^{+i*omega*t} * z
            ai += xs[j] * s + ys[j] * c;
        }
#pragma unroll
        for (int off = 16; off > 0; off >>= 1) {
            ar += __shfl_down_sync(0xffffffff, ar, off);
            ai += __shfl_down_sync(0xffffffff, ai, off);
        }
        if ((tid & 31) == 0) { swr[tid >> 5] = ar; swi[tid >> 5] = ai; }
        __syncthreads();
        if (tid == 0) {
            float tr = 0.f, ti = 0.f;
#pragma unroll
            for (int w = 0; w < 8; w++) { tr += swr[w]; ti += swi[w]; }
            g_part_r[b][split] = tr;
            g_part_i[b][split] = ti;
        }
    } else if (bx < NDFT + NTAB) {
        // Phase table: components of e^{i*omega*mu}, exact arg reduction.
        const int mu = (bx - NDFT) * 256 + tid;
        const int p  = (m * mu) & (NLEN - 1);
        float s, c;
        __sincosf(TWO_PI_OVER_N * (float)p, &s, &c);
        g_cos[mu] = c;
        g_sin[mu] = s;
    }

    // ---------------- Grid barrier (arrival) ----------------
    __syncthreads();
    if (tid == 0) {
        __threadfence();                       // publish partials / table
        int old = atomicAdd(&g_count, 1);
        if (old == NBLK - 1) {
            s_last = 1;
            atomicExch(&g_count, 0);           // reset for next graph replay
        }
    }
    __syncthreads();

    if (s_last) {
        // -------- Last arriver: reduce partials -> gated G[256] --------
        __threadfence();
        if (tid < NROWS) {
            float tr = 0.f, ti = 0.f;
#pragma unroll
            for (int sp = 0; sp < SPLIT; sp++) {
                tr += g_part_r[tid][sp];
                ti += g_part_i[tid][sp];
            }
            sZr[tid] = tr;
            sZi[tid] = ti;
        }
        __syncthreads();

        const int k  = tid >> 6;               // one thread per (k,co)
        const int co = tid & 63;
        float Gr = 0.f, Gi = 0.f;
#pragma unroll
        for (int ci = 0; ci < CIN; ci++) {
            const float a = fabsf(A[co * CIN + ci]);
            float sb, cb;
            __sincosf(beta[co * CIN + ci], &sb, &cb);
            const float Wr = a * cb, Wi = a * sb;
            const float Zr = sZr[k * CIN + ci];
            const float Zi = sZi[k * CIN + ci];
            Gr += Wr * Zr - Wi * Zi;
            Gi += Wr * Zi + Wi * Zr;
        }
        const float mag  = sqrtf(Gr * Gr + Gi * Gi);
        const float gate = (1.f / (1.f + __expf(-(mag + bias[co])))) / (mag + 1e-5f);
        g_Gr[tid] = gate * Gr;
        g_Gi[tid] = gate * Gi;
        __syncthreads();
        if (tid == 0) {
            __threadfence();                   // publish G before releasing
            atomicAdd(&g_flag, 1);
        }
    } else if (tid == 0) {
        // -------- Everyone else: spin until G is published --------
        while (*((volatile int*)&g_flag) == s_init) { }
    }
    __syncthreads();
    __threadfence();                            // acquire G

    // ---------------- Phase B: stream the output ----------------
    // block -> (output row b, half-row). out_r = Gr*c + Gi*s ; out_i = Gi*c - Gr*s.
    const int b    = bx >> 1;
    const int half = bx & 1;
    const float gr = g_Gr[b];
    const float gi = g_Gi[b];

    float* outr = out + (size_t)b * NLEN;
    float* outi = out + (size_t)NB * NLEN + (size_t)b * NLEN;

#pragma unroll
    for (int j = 0; j < 2; j++) {
        const int mu0 = half * 2048 + j * 1024 + tid * 4;
        const float4 c4 = *reinterpret_cast<const float4*>(&g_cos[mu0]);
        const float4 s4 = *reinterpret_cast<const float4*>(&g_sin[mu0]);

        float4 vr, vi;
        vr.x = gr * c4.x + gi * s4.x;  vi.x = gi * c4.x - gr * s4.x;
        vr.y = gr * c4.y + gi * s4.y;  vi.y = gi * c4.y - gr * s4.y;
        vr.z = gr * c4.z + gi * s4.z;  vi.z = gi * c4.z - gr * s4.z;
        vr.w = gr * c4.w + gi * s4.w;  vi.w = gi * c4.w - gr * s4.w;

        *reinterpret_cast<float4*>(outr + mu0) = vr;
        *reinterpret_cast<float4*>(outi + mu0) = vi;
    }
}

extern "C" void kernel_launch(void* const* d_in, const int* in_sizes, int n_in,
                              void* d_out, int out_size)
{
    const float* z_real = (const float*)d_in[0];
    const float* z_imag = (const float*)d_in[1];
    const float* A      = (const float*)d_in[2];
    const float* beta   = (const float*)d_in[3];
    const float* bias   = (const float*)d_in[4];
    const int*   mptr   = (const int*)d_in[5];
    float* out = (float*)d_out;

    fused_kernel<<<NBLK, 256>>>(z_real, z_imag, A, beta, bias, mptr, out);
}